// round 17
// baseline (speedup 1.0000x reference)
#include <cuda_runtime.h>
#include <cuda_fp16.h>
#include <cstdint>

#define Tn 512
#define Sn 1024
#define Bn 16
#define An 512
#define Hn 8

// ---------------- scratch (allocation-free) -----------------
// g_kh / g_vth pair-index storage is PERMUTED by perm8 so MMA B-operand word
// pairs (slot lam, slot lam+4) are adjacent -> LDS.64 in attn.
__device__ unsigned g_kh[128 * 1024 * 32];   // [bh][s][perm8(dpair)]
__device__ unsigned g_vth[128 * 64 * 512];   // [bh][d][perm8-within-64(spair)]
__device__ unsigned g_va[8192 * 256];        // [t*16+b][Apair] attn out (rn-fp16)
__device__ unsigned g_ow[512 * 256];         // [n][kpair]      (rn-fp16)
__device__ unsigned g_mbits[Bn * Tn * (Sn / 32)];  // bit-packed mask (1 = keep)
__device__ unsigned g_tile_ctr;              // attn work queue head

__device__ __forceinline__ int perm8(int p) {
    return (p & ~7) | ((p & 3) << 1) | ((p >> 2) & 1);
}

// ---------------- numeric helpers -----------------
__device__ __forceinline__ unsigned pkh(float a, float b) {
    unsigned r;
    asm("cvt.rn.f16x2.f32 %0, %1, %2;" : "=r"(r) : "f"(b), "f"(a));
    return r;
}

__device__ __forceinline__ void mma_f16(float c[4], const unsigned a[4], unsigned b0, unsigned b1) {
    asm volatile(
        "mma.sync.aligned.m16n8k16.row.col.f32.f16.f16.f32 "
        "{%0,%1,%2,%3}, {%4,%5,%6,%7}, {%8,%9}, {%0,%1,%2,%3};\n"
        : "+f"(c[0]), "+f"(c[1]), "+f"(c[2]), "+f"(c[3])
        : "r"(a[0]), "r"(a[1]), "r"(a[2]), "r"(a[3]), "r"(b0), "r"(b1));
}

// cp.async 16B
__device__ __forceinline__ void cp16(uint32_t sm_addr, const void* g) {
    asm volatile("cp.async.cg.shared.global [%0], [%1], 16;" :: "r"(sm_addr), "l"(g));
}
#define CP_COMMIT() asm volatile("cp.async.commit_group;" ::: "memory")
#define CP_WAIT1()  asm volatile("cp.async.wait_group 1;" ::: "memory")
#define CP_WAIT0()  asm volatile("cp.async.wait_group 0;" ::: "memory")

// ---------------- fused prep: vproj (+K fp16 emit) | mask bitpack | owprep --
// grid.x: [0,1024) vproj (bh = x>>3, ch = x&7); [1024,1536) mask; [1536,1544) ow.
#define VPK (128 * 36)
#define VPW (64 * 36)
#define VPV (128 * 37)
__global__ void __launch_bounds__(256) prep_kernel(const float* __restrict__ keys,
                                                   const float* __restrict__ vw,
                                                   const float* __restrict__ vb,
                                                   const unsigned* __restrict__ mask,
                                                   const float* __restrict__ ow) {
    const int tid = threadIdx.x;

    if (blockIdx.x >= 1024) {
        if (blockIdx.x < 1536) {
            // ---- mask bitpack: uint4 loads + nibble/shfl packing ----
            if (blockIdx.x == 1024 && tid == 0) g_tile_ctr = 0u;
            size_t base4 = (size_t)(blockIdx.x - 1024) * 4096;  // uint4 units
#pragma unroll 4
            for (int w = 0; w < 16; w++) {
                size_t uidx = base4 + (size_t)w * 256 + tid;
                uint4 v = ((const uint4*)mask)[uidx];
                unsigned nib = (v.x ? 1u : 0u) | (v.y ? 2u : 0u) |
                               (v.z ? 4u : 0u) | (v.w ? 8u : 0u);
                unsigned val = nib << (4 * (tid & 7));
                val |= __shfl_xor_sync(0xffffffffu, val, 1);
                val |= __shfl_xor_sync(0xffffffffu, val, 2);
                val |= __shfl_xor_sync(0xffffffffu, val, 4);
                if ((tid & 7) == 0) g_mbits[uidx >> 3] = val;
            }
        } else {
            // ---- owprep: 8 blocks x 16384 pairs (float4 loads) ----
            size_t base = (size_t)(blockIdx.x - 1536) * 16384;
#pragma unroll 4
            for (int w = 0; w < 32; w++) {
                size_t p = base + ((size_t)w * 256 + tid) * 2;
                float4 v = *(const float4*)(ow + 2 * p);
                *(uint2*)&g_ow[p] = make_uint2(pkh(v.x, v.y), pkh(v.z, v.w));
            }
        }
        return;
    }

    // ---- vproj via fp16 MMA ----
    extern __shared__ unsigned smv[];
    unsigned* kf = smv;                 // [128][36] K fp16 pairs [s][jpair] (standard order)
    unsigned* wf = smv + VPK;           // [64][36]  vw fp16 pairs [d][jpair]
    unsigned* vh_sm = smv + VPK + VPW;  // [128][37] vh fp16 pairs [s][dpair]

    const int bh = blockIdx.x >> 3, ch = blockIdx.x & 7;
    const int b = bh >> 3, h = bh & 7;
    const int s0 = ch * 128;
    const int wid = tid >> 5, lane = tid & 31;
    const int g = lane >> 2, lam = lane & 3;
    const int wt = wid * 16;

    for (int i = tid; i < 128 * 16; i += 256) {
        int r = i >> 4, c = (i & 15) * 2;
        float4 v = *(const float4*)(keys + ((size_t)(s0 + r) * 16 + b) * 512 + h * 64 + 2 * c);
        kf[r * 36 + c] = pkh(v.x, v.y);
        kf[r * 36 + c + 1] = pkh(v.z, v.w);
    }
    for (int i = tid; i < 64 * 16; i += 256) {
        int r = i >> 4, c = (i & 15) * 2;
        float4 v = *(const float4*)(vw + (size_t)r * 64 + 2 * c);
        wf[r * 36 + c] = pkh(v.x, v.y);
        wf[r * 36 + c + 1] = pkh(v.z, v.w);
    }
    __syncthreads();

    // emit K fp16 with perm8 pair ordering
    for (int i = tid; i < 128 * 32; i += 256) {
        int r = i >> 5, c = i & 31;
        g_kh[((size_t)bh * 1024 + s0 + r) * 32 + perm8(c)] = kf[r * 36 + c];
    }

    unsigned af[4][4];
#pragma unroll
    for (int kq = 0; kq < 4; kq++) {
        int row = wt + g;
        af[kq][0] = kf[row * 36 + 8 * kq + lam];
        af[kq][1] = kf[(row + 8) * 36 + 8 * kq + lam];
        af[kq][2] = kf[row * 36 + 8 * kq + 4 + lam];
        af[kq][3] = kf[(row + 8) * 36 + 8 * kq + 4 + lam];
    }

    float acc[8][4];
#pragma unroll
    for (int nt = 0; nt < 8; nt++) {
        float2 bv = *(const float2*)(vb + 8 * nt + 2 * lam);
        acc[nt][0] = bv.x; acc[nt][1] = bv.y;
        acc[nt][2] = bv.x; acc[nt][3] = bv.y;
    }
#pragma unroll
    for (int nt = 0; nt < 8; nt++)
#pragma unroll
        for (int kq = 0; kq < 4; kq++) {
            unsigned B0 = wf[(8 * nt + g) * 36 + 8 * kq + lam];
            unsigned B1 = wf[(8 * nt + g) * 36 + 8 * kq + 4 + lam];
            mma_f16(acc[nt], af[kq], B0, B1);
        }

#pragma unroll
    for (int nt = 0; nt < 8; nt++) {
        int dp = 4 * nt + lam;
        vh_sm[(wt + g) * 37 + dp] = pkh(acc[nt][0], acc[nt][1]);
        vh_sm[(wt + g + 8) * 37 + dp] = pkh(acc[nt][2], acc[nt][3]);
    }
    __syncthreads();

    // transpose-pack to g_vth[d][spair], perm8 applied to spair (within 64-chunk)
    const unsigned short* vh_h = (const unsigned short*)vh_sm;  // pitch 74 halves
    for (int i = tid; i < 64 * 64; i += 256) {
        int d = i >> 6, sp = i & 63;
        unsigned lo = vh_h[(2 * sp) * 74 + d];
        unsigned hi = vh_h[(2 * sp + 1) * 74 + d];
        g_vth[((size_t)bh * 64 + d) * 512 + ch * 64 + perm8(sp)] = lo | (hi << 16);
    }
}

// ---------------- flash attention (fp16 MMA, LDS.64 operands, persistent) ---
#define KPITCH 40
#define VPITCH 72
#define KBUF (128 * KPITCH)
#define VBUF (64 * VPITCH)
#define BUFSZ (KBUF + VBUF)

template <bool FULL>
__device__ __forceinline__ void attn_iter(const unsigned* __restrict__ k_sm,
                                          const unsigned* __restrict__ v_sm,
                                          const unsigned qf[4][4], float oacc[8][4],
                                          float& lA, float& lB,
                                          const unsigned* wArr, const unsigned* wBrr,
                                          int g, int lam) {
#pragma unroll
    for (int kt = 0; kt < 8; kt++) {
        unsigned pf4[4];
#pragma unroll
        for (int jj = 0; jj < 2; jj++) {
            const int j = 2 * kt + jj;
            float sa[4] = {0.0f, 0.0f, 0.0f, 0.0f};
            float sb[4] = {0.0f, 0.0f, 0.0f, 0.0f};
            {
                const unsigned* kr = k_sm + (8 * j + g) * KPITCH + 2 * lam;
                uint2 B0 = *(const uint2*)&kr[0];
                uint2 B1 = *(const uint2*)&kr[8];
                uint2 B2 = *(const uint2*)&kr[16];
                uint2 B3 = *(const uint2*)&kr[24];
                mma_f16(sa, qf[0], B0.x, B0.y);
                mma_f16(sa, qf[1], B1.x, B1.y);
                mma_f16(sb, qf[2], B2.x, B2.y);
                mma_f16(sb, qf[3], B3.x, B3.y);
            }
            float s0v = sa[0] + sb[0], s1v = sa[1] + sb[1];
            float s2v = sa[2] + sb[2], s3v = sa[3] + sb[3];
            float p0, p1, p2, p3;
            if (FULL) {
                p0 = __expf(s0v); p1 = __expf(s1v);
                p2 = __expf(s2v); p3 = __expf(s3v);
            } else {
                int sh = 8 * (j & 3) + 2 * lam;
                unsigned wA = wArr[j >> 2], wB = wBrr[j >> 2];
                p0 = ((wA >> sh) & 1u) ? __expf(s0v) : 0.0f;
                p1 = ((wA >> (sh + 1)) & 1u) ? __expf(s1v) : 0.0f;
                p2 = ((wB >> sh) & 1u) ? __expf(s2v) : 0.0f;
                p3 = ((wB >> (sh + 1)) & 1u) ? __expf(s3v) : 0.0f;
            }
            lA += p0 + p1; lB += p2 + p3;
            pf4[jj * 2] = pkh(p0, p1);
            pf4[jj * 2 + 1] = pkh(p2, p3);
        }
#pragma unroll
        for (int nt = 0; nt < 8; nt++) {
            uint2 Bv = *(const uint2*)&v_sm[(8 * nt + g) * VPITCH + 8 * kt + 2 * lam];
            mma_f16(oacc[nt], pf4, Bv.x, Bv.y);
        }
    }
}

__global__ void __launch_bounds__(256, 2) attn_kernel(const float* __restrict__ q) {
    extern __shared__ unsigned sm1[];
    __shared__ unsigned tile_s;

    const int tid = threadIdx.x, wid = tid >> 5, lane = tid & 31;
    const int g = lane >> 2, lam = lane & 3;
    const int wt = wid * 16;
    const uint32_t sm_base = (uint32_t)__cvta_generic_to_shared(sm1);

    while (true) {
        if (tid == 0) tile_s = atomicAdd(&g_tile_ctr, 1u);
        __syncthreads();
        const unsigned tile = tile_s;
        if (tile >= 512u) return;

        const int t0 = (int)(tile & 3u) * 128;
        const int h = (int)(tile >> 2) & 7;
        const int b = (int)(tile >> 5);
        const int bh = b * 8 + h;

        // stage Q into buf1's K region (perm8 pair ordering), extract frags
        {
            unsigned* qs = sm1 + BUFSZ;
            for (int i = tid; i < 128 * 16; i += 256) {
                int r = i >> 4, c = (i & 15) * 2;
                float4 v = *(const float4*)(q + ((size_t)(t0 + r) * 16 + b) * 512 + h * 64 + 2 * c);
                qs[r * KPITCH + perm8(c)] = pkh(v.x * 0.125f, v.y * 0.125f);
                qs[r * KPITCH + perm8(c + 1)] = pkh(v.z * 0.125f, v.w * 0.125f);
            }
        }
        __syncthreads();
        unsigned qf[4][4];
#pragma unroll
        for (int kt = 0; kt < 4; kt++) {
            const unsigned* qs = sm1 + BUFSZ;
            int row = wt + g;
            uint2 u0 = *(const uint2*)&qs[row * KPITCH + 8 * kt + 2 * lam];
            uint2 u1 = *(const uint2*)&qs[(row + 8) * KPITCH + 8 * kt + 2 * lam];
            qf[kt][0] = u0.x; qf[kt][2] = u0.y;
            qf[kt][1] = u1.x; qf[kt][3] = u1.y;
        }

        float oacc[8][4];
#pragma unroll
        for (int nt = 0; nt < 8; nt++)
#pragma unroll
            for (int c = 0; c < 4; c++) oacc[nt][c] = 0.0f;
        float lA = 0.0f, lB = 0.0f;

        const unsigned* mbA = g_mbits + ((size_t)b * Tn + t0 + wt + g) * 32;
        const unsigned* mbB = mbA + 8 * 32;

        auto stage = [&](int st, int bf) {
            uint32_t kb = sm_base + (bf * BUFSZ) * 4;
            uint32_t vbuf = kb + KBUF * 4;
            const unsigned* kg = g_kh + ((size_t)bh * 1024 + st * 128) * 32;
            const unsigned* vg = g_vth + (size_t)bh * 64 * 512 + st * 64;
#pragma unroll
            for (int i = tid; i < 128 * 8; i += 256) {
                int r = i >> 3, c = i & 7;
                cp16(kb + (r * KPITCH + c * 4) * 4, kg + r * 32 + c * 4);
            }
#pragma unroll
            for (int i = tid; i < 64 * 16; i += 256) {
                int r = i >> 4, c = i & 15;
                cp16(vbuf + (r * VPITCH + c * 4) * 4, vg + (size_t)r * 512 + c * 4);
            }
        };

        __syncthreads();
        stage(0, 0);
        CP_COMMIT();

        for (int st = 0; st < 8; st++) {
            const int cur = st & 1;
            __syncthreads();
            if (st < 7) {
                stage(st + 1, 1 - cur);
                CP_COMMIT();
                CP_WAIT1();
            } else {
                CP_WAIT0();
            }
            __syncthreads();

            const unsigned* k_sm = sm1 + cur * BUFSZ;
            const unsigned* v_sm = k_sm + KBUF;

            uint4 mwA = *(const uint4*)(mbA + st * 4);
            uint4 mwB = *(const uint4*)(mbB + st * 4);
            const unsigned wArr[4] = {mwA.x, mwA.y, mwA.z, mwA.w};
            const unsigned wBrr[4] = {mwB.x, mwB.y, mwB.z, mwB.w};
            const bool full = (mwA.x & mwA.y & mwA.z & mwA.w &
                               mwB.x & mwB.y & mwB.z & mwB.w) == 0xFFFFFFFFu;

            if (full)
                attn_iter<true>(k_sm, v_sm, qf, oacc, lA, lB, wArr, wBrr, g, lam);
            else
                attn_iter<false>(k_sm, v_sm, qf, oacc, lA, lB, wArr, wBrr, g, lam);
        }

        lA += __shfl_xor_sync(0xffffffffu, lA, 1);
        lA += __shfl_xor_sync(0xffffffffu, lA, 2);
        lB += __shfl_xor_sync(0xffffffffu, lB, 1);
        lB += __shfl_xor_sync(0xffffffffu, lB, 2);
        float iA = 1.0f / lA, iB = 1.0f / lB;
        int tA = t0 + wt + g;
        int apair = h * 32 + lam;
#pragma unroll
        for (int nt = 0; nt < 8; nt++) {
            g_va[((size_t)tA * 16 + b) * 256 + apair + nt * 4] =
                pkh(oacc[nt][0] * iA, oacc[nt][1] * iA);
            g_va[((size_t)(tA + 8) * 16 + b) * 256 + apair + nt * 4] =
                pkh(oacc[nt][2] * iB, oacc[nt][3] * iB);
        }
    }
}

// ---------------- oproj (fp16 MMA + cp.async double buffer) -----------------
#define OABUF (128 * 36)
#define OBUFSZ (2 * OABUF)  // a + b per stage

__global__ void __launch_bounds__(256, 2) oproj_kernel(const float* __restrict__ ob,
                                                       float* __restrict__ out) {
    extern __shared__ unsigned smo[];

    const int tid = threadIdx.x, wid = tid >> 5, lane = tid & 31;
    const int g = lane >> 2, lam = lane & 3;
    const int mw = wid >> 1, nw = wid & 1;
    const int row0 = blockIdx.x * 128, n0 = blockIdx.y * 128;
    const uint32_t sm_base = (uint32_t)__cvta_generic_to_shared(smo);

    float acc[2][8][4];
#pragma unroll
    for (int mt = 0; mt < 2; mt++)
#pragma unroll
        for (int nt = 0; nt < 8; nt++) {
            float2 bv = *(const float2*)(ob + n0 + nw * 64 + 8 * nt + 2 * lam);
            acc[mt][nt][0] = bv.x; acc[mt][nt][1] = bv.y;
            acc[mt][nt][2] = bv.x; acc[mt][nt][3] = bv.y;
        }

    auto stage = [&](int kc, int bf) {
        uint32_t ab = sm_base + (bf * OBUFSZ) * 4;
        uint32_t bb = ab + OABUF * 4;
        const unsigned* ag = g_va + (size_t)row0 * 256 + 32 * kc;
        const unsigned* bg = g_ow + (size_t)n0 * 256 + 32 * kc;
#pragma unroll
        for (int i = tid; i < 128 * 8; i += 256) {
            int r = i >> 3, c = i & 7;
            cp16(ab + (r * 36 + c * 4) * 4, ag + (size_t)r * 256 + c * 4);
            cp16(bb + (r * 36 + c * 4) * 4, bg + (size_t)r * 256 + c * 4);
        }
    };

    stage(0, 0);
    CP_COMMIT();

    for (int kc = 0; kc < 8; kc++) {
        const int cur = kc & 1;
        __syncthreads();
        if (kc < 7) {
            stage(kc + 1, 1 - cur);
            CP_COMMIT();
            CP_WAIT1();
        } else {
            CP_WAIT0();
        }
        __syncthreads();

        const unsigned* a_sm = smo + cur * OBUFSZ;
        const unsigned* b_sm = a_sm + OABUF;

        unsigned af[2][4][4];
#pragma unroll
        for (int mt = 0; mt < 2; mt++)
#pragma unroll
            for (int kt = 0; kt < 4; kt++) {
                int row = mw * 32 + mt * 16 + g;
                af[mt][kt][0] = a_sm[row * 36 + 8 * kt + lam];
                af[mt][kt][1] = a_sm[(row + 8) * 36 + 8 * kt + lam];
                af[mt][kt][2] = a_sm[row * 36 + 8 * kt + 4 + lam];
                af[mt][kt][3] = a_sm[(row + 8) * 36 + 8 * kt + 4 + lam];
            }

#pragma unroll
        for (int nt = 0; nt < 8; nt++)
#pragma unroll
            for (int kt = 0; kt < 4; kt++) {
                unsigned B0 = b_sm[(nw * 64 + 8 * nt + g) * 36 + 8 * kt + lam];
                unsigned B1 = b_sm[(nw * 64 + 8 * nt + g) * 36 + 8 * kt + 4 + lam];
#pragma unroll
                for (int mt = 0; mt < 2; mt++)
                    mma_f16(acc[mt][nt], af[mt][kt], B0, B1);
            }
    }

#pragma unroll
    for (int mt = 0; mt < 2; mt++)
#pragma unroll
        for (int nt = 0; nt < 8; nt++) {
            int row = row0 + mw * 32 + mt * 16 + g;
            int col = n0 + nw * 64 + 8 * nt + 2 * lam;
            *(float2*)&out[(size_t)row * 512 + col] = make_float2(acc[mt][nt][0], acc[mt][nt][1]);
            *(float2*)&out[(size_t)(row + 8) * 512 + col] = make_float2(acc[mt][nt][2], acc[mt][nt][3]);
        }
}

// ---------------------------------------------------------------------------
extern "C" void kernel_launch(void* const* d_in, const int* in_sizes, int n_in,
                              void* d_out, int out_size) {
    const float* q = (const float*)d_in[0];
    const float* k = (const float*)d_in[1];
    const unsigned* mask = (const unsigned*)d_in[2];
    const float* vw = (const float*)d_in[3];
    const float* vb = (const float*)d_in[4];
    const float* ow = (const float*)d_in[5];
    const float* ob = (const float*)d_in[6];
    float* out = (float*)d_out;

    const int prep_smem = (VPK + VPW + VPV) * sizeof(unsigned);  // 46592
    cudaFuncSetAttribute(prep_kernel, cudaFuncAttributeMaxDynamicSharedMemorySize, prep_smem);
    prep_kernel<<<1544, 256, prep_smem>>>(k, vw, vb, mask, ow);

    const int attn_smem = 2 * BUFSZ * sizeof(unsigned);  // 77824
    cudaFuncSetAttribute(attn_kernel, cudaFuncAttributeMaxDynamicSharedMemorySize, attn_smem);
    attn_kernel<<<304, 256, attn_smem>>>(q);  // persistent, 2/SM on 152 SMs

    const int oproj_smem = 2 * OBUFSZ * sizeof(unsigned);  // 73728
    cudaFuncSetAttribute(oproj_kernel, cudaFuncAttributeMaxDynamicSharedMemorySize, oproj_smem);
    oproj_kernel<<<dim3(64, 4), 256, oproj_smem>>>(ob, out);
}